// round 4
// baseline (speedup 1.0000x reference)
#include <cuda_runtime.h>

#define BDIM 8
#define NDIM 2048
#define DDIM 512
#define P_ASEM 0.6f

#define TPB 256
#define CTAS_PER_SM 8
#define NSM 148
#define GRID (NSM * CTAS_PER_SM)   // 1184 resident CTAs, occupancy-guaranteed

// Scratch: esi[b*N+i] = exp(-(si+bias)), esj[b*N+j] = exp(-sj)
__device__ float g_esi[BDIM * NDIM];
__device__ float g_esj[BDIM * NDIM];
__device__ unsigned g_bar = 0;     // monotonically increasing across replays

__global__ void __launch_bounds__(TPB, CTAS_PER_SM)
fused_all(const float* __restrict__ x,
          const float* __restrict__ adj,
          const float* __restrict__ W,
          const float* __restrict__ bias,
          float* __restrict__ out) {
    const unsigned tid = threadIdx.x;
    const unsigned wid = tid >> 5;
    const unsigned lane = tid & 31;
    const unsigned nwarps = gridDim.x * (TPB / 32);

    // ---------------- Phase 1: row dots -> exp tables ----------------
    const float4* Wi4 = reinterpret_cast<const float4*>(W);
    const float4* Wj4 = reinterpret_cast<const float4*>(W + DDIM);
    for (unsigned row = blockIdx.x * (TPB / 32) + wid; row < BDIM * NDIM; row += nwarps) {
        const float4* xr = reinterpret_cast<const float4*>(x + (size_t)row * DDIM);
        float si = 0.f, sj = 0.f;
#pragma unroll
        for (int k = 0; k < DDIM / 4 / 32; k++) {
            int d4 = lane + k * 32;
            float4 xv = xr[d4];
            float4 wi = Wi4[d4];
            float4 wj = Wj4[d4];
            si += xv.x * wi.x + xv.y * wi.y + xv.z * wi.z + xv.w * wi.w;
            sj += xv.x * wj.x + xv.y * wj.y + xv.z * wj.z + xv.w * wj.w;
        }
#pragma unroll
        for (int o = 16; o; o >>= 1) {
            si += __shfl_down_sync(0xffffffffu, si, o);
            sj += __shfl_down_sync(0xffffffffu, sj, o);
        }
        if (lane == 0) {
            g_esi[row] = __expf(-(si + bias[0]));
            g_esj[row] = __expf(-sj);
        }
    }

    // ---------------- Software grid barrier (replay-safe) ----------------
    __threadfence();               // publish phase-1 writes
    __syncthreads();
    if (tid == 0) {
        unsigned v = atomicAdd(&g_bar, 1u);
        unsigned target = (v / gridDim.x + 1u) * gridDim.x;
        while (*(volatile unsigned*)&g_bar < target) { }
    }
    __syncthreads();
    __threadfence();               // acquire

    // ---------------- Phase 2: fuse ----------------
    // One row (2048 floats = 512 float4) per block iteration; 2 float4/thread.
    for (unsigned row = blockIdx.x; row < BDIM * NDIM; row += gridDim.x) {
        unsigned b_base = row & ~(NDIM - 1u);
        float esi = g_esi[row];

        const float4* adj_row = reinterpret_cast<const float4*>(adj) + (size_t)row * (NDIM / 4);
        float4* out_row = reinterpret_cast<float4*>(out) + (size_t)row * (NDIM / 4);
        const float4* esj_row = reinterpret_cast<const float4*>(g_esj + b_base);

        float4 a0 = __ldg(adj_row + tid);
        float4 a1 = __ldg(adj_row + tid + TPB);
        float4 e0 = esj_row[tid];
        float4 e1 = esj_row[tid + TPB];

        float4 o0, o1;
        o0.x = fmaf(P_ASEM, __frcp_rn(fmaf(esi, e0.x, 1.0f)), (1.0f - P_ASEM) * a0.x);
        o0.y = fmaf(P_ASEM, __frcp_rn(fmaf(esi, e0.y, 1.0f)), (1.0f - P_ASEM) * a0.y);
        o0.z = fmaf(P_ASEM, __frcp_rn(fmaf(esi, e0.z, 1.0f)), (1.0f - P_ASEM) * a0.z);
        o0.w = fmaf(P_ASEM, __frcp_rn(fmaf(esi, e0.w, 1.0f)), (1.0f - P_ASEM) * a0.w);
        o1.x = fmaf(P_ASEM, __frcp_rn(fmaf(esi, e1.x, 1.0f)), (1.0f - P_ASEM) * a1.x);
        o1.y = fmaf(P_ASEM, __frcp_rn(fmaf(esi, e1.y, 1.0f)), (1.0f - P_ASEM) * a1.y);
        o1.z = fmaf(P_ASEM, __frcp_rn(fmaf(esi, e1.z, 1.0f)), (1.0f - P_ASEM) * a1.z);
        o1.w = fmaf(P_ASEM, __frcp_rn(fmaf(esi, e1.w, 1.0f)), (1.0f - P_ASEM) * a1.w);

        out_row[tid] = o0;
        out_row[tid + TPB] = o1;
    }
}

extern "C" void kernel_launch(void* const* d_in, const int* in_sizes, int n_in,
                              void* d_out, int out_size) {
    const float* x   = (const float*)d_in[0];  // (8, 2048, 512)
    const float* adj = (const float*)d_in[1];  // (8, 2048, 2048)
    const float* W   = (const float*)d_in[2];  // (1, 1024)
    const float* b   = (const float*)d_in[3];  // (1,)
    float* out = (float*)d_out;

    fused_all<<<GRID, TPB>>>(x, adj, W, b, out);
}

// round 5
// speedup vs baseline: 1.3264x; 1.3264x over previous
#include <cuda_runtime.h>

#define BDIM 8
#define NDIM 2048
#define DDIM 512
#define P_ASEM 0.6f

// Scratch: esi[b*N+i] = exp(-(si+bias)), esj[b*N+j] = exp(-sj)
__device__ float g_esi[BDIM * NDIM];
__device__ float g_esj[BDIM * NDIM];

// Kernel 1: one warp per row. si = x_row . Wi + b, sj = x_row . Wj,
// stored as exp(-si), exp(-sj).
__global__ void row_dots_kernel(const float* __restrict__ x,
                                const float* __restrict__ W,
                                const float* __restrict__ bias) {
    int warp_id = (blockIdx.x * blockDim.x + threadIdx.x) >> 5;
    int lane = threadIdx.x & 31;
    if (warp_id >= BDIM * NDIM) return;

    const float4* xr = reinterpret_cast<const float4*>(x + (size_t)warp_id * DDIM);
    const float4* Wi = reinterpret_cast<const float4*>(W);
    const float4* Wj = reinterpret_cast<const float4*>(W + DDIM);

    float si = 0.f, sj = 0.f;
#pragma unroll
    for (int k = 0; k < DDIM / 4 / 32; k++) {
        int d4 = lane + k * 32;
        float4 xv = xr[d4];
        float4 wi = Wi[d4];
        float4 wj = Wj[d4];
        si += xv.x * wi.x + xv.y * wi.y + xv.z * wi.z + xv.w * wi.w;
        sj += xv.x * wj.x + xv.y * wj.y + xv.z * wj.z + xv.w * wj.w;
    }
#pragma unroll
    for (int o = 16; o; o >>= 1) {
        si += __shfl_down_sync(0xffffffffu, si, o);
        sj += __shfl_down_sync(0xffffffffu, sj, o);
    }
    if (lane == 0) {
        g_esi[warp_id] = __expf(-(si + bias[0]));
        g_esj[warp_id] = __expf(-sj);
    }
}

__device__ __forceinline__ float blend(float esi, float esj, float a) {
    // P * sigmoid(si+sj) + (1-P)*a, with sigmoid = 1/(1+esi*esj)
    return fmaf(P_ASEM, __frcp_rn(fmaf(esi, esj, 1.0f)), (1.0f - P_ASEM) * a);
}

// Kernel 2: one block per 2 consecutive rows (same batch).
// esj float4s loaded once serve both rows; 4 adj loads front-batched.
// Streaming hints: adj read-once (__ldcs), out write-once (__stcs).
__global__ void __launch_bounds__(256) fuse_kernel(const float* __restrict__ adj,
                                                   float* __restrict__ out) {
    unsigned row0 = blockIdx.x * 2u;         // b*2048 + i, i even
    unsigned b_base = row0 & ~(NDIM - 1u);   // b*2048
    unsigned tid = threadIdx.x;

    float esi0 = g_esi[row0];
    float esi1 = g_esi[row0 + 1];

    const float4* adj0 = reinterpret_cast<const float4*>(adj) + (size_t)row0 * (NDIM / 4);
    const float4* adj1 = adj0 + (NDIM / 4);
    float4* out0 = reinterpret_cast<float4*>(out) + (size_t)row0 * (NDIM / 4);
    float4* out1 = out0 + (NDIM / 4);
    const float4* esj_row = reinterpret_cast<const float4*>(g_esj + b_base);

    // front-batched: 4 adj + 2 esj loads in flight
    float4 a00 = __ldcs(adj0 + tid);
    float4 a01 = __ldcs(adj0 + tid + 256);
    float4 a10 = __ldcs(adj1 + tid);
    float4 a11 = __ldcs(adj1 + tid + 256);
    float4 e0 = esj_row[tid];
    float4 e1 = esj_row[tid + 256];

    float4 o;
    o.x = blend(esi0, e0.x, a00.x);
    o.y = blend(esi0, e0.y, a00.y);
    o.z = blend(esi0, e0.z, a00.z);
    o.w = blend(esi0, e0.w, a00.w);
    __stcs(out0 + tid, o);

    o.x = blend(esi0, e1.x, a01.x);
    o.y = blend(esi0, e1.y, a01.y);
    o.z = blend(esi0, e1.z, a01.z);
    o.w = blend(esi0, e1.w, a01.w);
    __stcs(out0 + tid + 256, o);

    o.x = blend(esi1, e0.x, a10.x);
    o.y = blend(esi1, e0.y, a10.y);
    o.z = blend(esi1, e0.z, a10.z);
    o.w = blend(esi1, e0.w, a10.w);
    __stcs(out1 + tid, o);

    o.x = blend(esi1, e1.x, a11.x);
    o.y = blend(esi1, e1.y, a11.y);
    o.z = blend(esi1, e1.z, a11.z);
    o.w = blend(esi1, e1.w, a11.w);
    __stcs(out1 + tid + 256, o);
}

extern "C" void kernel_launch(void* const* d_in, const int* in_sizes, int n_in,
                              void* d_out, int out_size) {
    const float* x   = (const float*)d_in[0];  // (8, 2048, 512)
    const float* adj = (const float*)d_in[1];  // (8, 2048, 2048)
    const float* W   = (const float*)d_in[2];  // (1, 1024)
    const float* b   = (const float*)d_in[3];  // (1,)
    float* out = (float*)d_out;

    // Kernel 1: 16384 rows, 8 warps/block -> 2048 blocks
    {
        int threads = 256;
        int rows = BDIM * NDIM;
        int warps_per_block = threads / 32;
        int blocks = (rows + warps_per_block - 1) / warps_per_block;
        row_dots_kernel<<<blocks, threads>>>(x, W, b);
    }
    // Kernel 2: 2 rows per block -> 8192 blocks
    fuse_kernel<<<BDIM * NDIM / 2, 256>>>(adj, out);
}

// round 6
// speedup vs baseline: 1.3748x; 1.0364x over previous
#include <cuda_runtime.h>

#define BDIM 8
#define NDIM 2048
#define DDIM 512
#define P_ASEM 0.6f

// Scratch: esi[b*N+i] = exp(-(si+bias)), esj[b*N+j] = exp(-sj)
__device__ float g_esi[BDIM * NDIM];
__device__ float g_esj[BDIM * NDIM];

// Kernel 1: one warp per 2 rows (8 x-loads in flight per lane).
__global__ void row_dots_kernel(const float* __restrict__ x,
                                const float* __restrict__ W,
                                const float* __restrict__ bias) {
    int warp_id = (blockIdx.x * blockDim.x + threadIdx.x) >> 5;
    int lane = threadIdx.x & 31;
    int row0 = warp_id * 2;
    if (row0 >= BDIM * NDIM) return;

    const float4* xr0 = reinterpret_cast<const float4*>(x + (size_t)row0 * DDIM);
    const float4* xr1 = xr0 + (DDIM / 4);
    const float4* Wi = reinterpret_cast<const float4*>(W);
    const float4* Wj = reinterpret_cast<const float4*>(W + DDIM);

    float si0 = 0.f, sj0 = 0.f, si1 = 0.f, sj1 = 0.f;
#pragma unroll
    for (int k = 0; k < DDIM / 4 / 32; k++) {
        int d4 = lane + k * 32;
        float4 x0 = xr0[d4];
        float4 x1 = xr1[d4];
        float4 wi = Wi[d4];
        float4 wj = Wj[d4];
        si0 += x0.x * wi.x + x0.y * wi.y + x0.z * wi.z + x0.w * wi.w;
        sj0 += x0.x * wj.x + x0.y * wj.y + x0.z * wj.z + x0.w * wj.w;
        si1 += x1.x * wi.x + x1.y * wi.y + x1.z * wi.z + x1.w * wi.w;
        sj1 += x1.x * wj.x + x1.y * wj.y + x1.z * wj.z + x1.w * wj.w;
    }
#pragma unroll
    for (int o = 16; o; o >>= 1) {
        si0 += __shfl_down_sync(0xffffffffu, si0, o);
        sj0 += __shfl_down_sync(0xffffffffu, sj0, o);
        si1 += __shfl_down_sync(0xffffffffu, si1, o);
        sj1 += __shfl_down_sync(0xffffffffu, sj1, o);
    }
    if (lane == 0) {
        float b0 = bias[0];
        g_esi[row0]     = __expf(-(si0 + b0));
        g_esj[row0]     = __expf(-sj0);
        g_esi[row0 + 1] = __expf(-(si1 + b0));
        g_esj[row0 + 1] = __expf(-sj1);
    }
}

__device__ __forceinline__ float blend(float esi, float esj, float a) {
    // P * sigmoid(si+sj) + (1-P)*a, with sigmoid = 1/(1+esi*esj)
    return fmaf(P_ASEM, __frcp_rn(fmaf(esi, esj, 1.0f)), (1.0f - P_ASEM) * a);
}

// Kernel 2: 4 consecutive rows (same batch) per 512-thread block.
// Each thread: ONE esj float4 reused across 4 rows; 4 independent adj loads
// front-batched; 4 stores. 2048 floats/row = 512 float4 = exactly blockDim.
__global__ void __launch_bounds__(512) fuse_kernel(const float* __restrict__ adj,
                                                   float* __restrict__ out) {
    unsigned row0 = blockIdx.x * 4u;         // b*2048 + i, i multiple of 4
    unsigned b_base = row0 & ~(NDIM - 1u);   // b*2048
    unsigned tid = threadIdx.x;

    float esi0 = g_esi[row0];
    float esi1 = g_esi[row0 + 1];
    float esi2 = g_esi[row0 + 2];
    float esi3 = g_esi[row0 + 3];

    const float4* adj0 = reinterpret_cast<const float4*>(adj) + (size_t)row0 * (NDIM / 4);
    float4* out0 = reinterpret_cast<float4*>(out) + (size_t)row0 * (NDIM / 4);
    const float4* esj_row = reinterpret_cast<const float4*>(g_esj + b_base);

    // front-batched independent loads
    float4 e  = esj_row[tid];
    float4 a0 = __ldcs(adj0 + tid);
    float4 a1 = __ldcs(adj0 + tid + 512);
    float4 a2 = __ldcs(adj0 + tid + 1024);
    float4 a3 = __ldcs(adj0 + tid + 1536);

    float4 o;
    o.x = blend(esi0, e.x, a0.x);
    o.y = blend(esi0, e.y, a0.y);
    o.z = blend(esi0, e.z, a0.z);
    o.w = blend(esi0, e.w, a0.w);
    __stcs(out0 + tid, o);

    o.x = blend(esi1, e.x, a1.x);
    o.y = blend(esi1, e.y, a1.y);
    o.z = blend(esi1, e.z, a1.z);
    o.w = blend(esi1, e.w, a1.w);
    __stcs(out0 + tid + 512, o);

    o.x = blend(esi2, e.x, a2.x);
    o.y = blend(esi2, e.y, a2.y);
    o.z = blend(esi2, e.z, a2.z);
    o.w = blend(esi2, e.w, a2.w);
    __stcs(out0 + tid + 1024, o);

    o.x = blend(esi3, e.x, a3.x);
    o.y = blend(esi3, e.y, a3.y);
    o.z = blend(esi3, e.z, a3.z);
    o.w = blend(esi3, e.w, a3.w);
    __stcs(out0 + tid + 1536, o);
}

extern "C" void kernel_launch(void* const* d_in, const int* in_sizes, int n_in,
                              void* d_out, int out_size) {
    const float* x   = (const float*)d_in[0];  // (8, 2048, 512)
    const float* adj = (const float*)d_in[1];  // (8, 2048, 2048)
    const float* W   = (const float*)d_in[2];  // (1, 1024)
    const float* b   = (const float*)d_in[3];  // (1,)
    float* out = (float*)d_out;

    // Kernel 1: 16384 rows, 2 rows/warp, 8 warps/block -> 1024 blocks
    row_dots_kernel<<<1024, 256>>>(x, W, b);
    // Kernel 2: 4 rows per block -> 4096 blocks of 512 threads
    fuse_kernel<<<BDIM * NDIM / 4, 512>>>(adj, out);
}

// round 7
// speedup vs baseline: 1.3774x; 1.0020x over previous
#include <cuda_runtime.h>

#define BDIM 8
#define NDIM 2048
#define DDIM 512
#define P_ASEM 0.6f

// Scratch: esi[b*N+i] = exp(-(si+bias)), esj[b*N+j] = exp(-sj)
__device__ float g_esi[BDIM * NDIM];
__device__ float g_esj[BDIM * NDIM];

// Kernel 1: one warp per 4 rows (16 x-loads in flight per lane per iter).
// 16384 rows / 4 = 4096 warps = 512 blocks -> single resident wave.
__global__ void row_dots_kernel(const float* __restrict__ x,
                                const float* __restrict__ W,
                                const float* __restrict__ bias) {
    int warp_id = (blockIdx.x * blockDim.x + threadIdx.x) >> 5;
    int lane = threadIdx.x & 31;
    int row0 = warp_id * 4;
    if (row0 >= BDIM * NDIM) return;

    const float4* xr0 = reinterpret_cast<const float4*>(x + (size_t)row0 * DDIM);
    const float4* xr1 = xr0 + (DDIM / 4);
    const float4* xr2 = xr1 + (DDIM / 4);
    const float4* xr3 = xr2 + (DDIM / 4);
    const float4* Wi = reinterpret_cast<const float4*>(W);
    const float4* Wj = reinterpret_cast<const float4*>(W + DDIM);

    float si0 = 0.f, sj0 = 0.f, si1 = 0.f, sj1 = 0.f;
    float si2 = 0.f, sj2 = 0.f, si3 = 0.f, sj3 = 0.f;
#pragma unroll
    for (int k = 0; k < DDIM / 4 / 32; k++) {
        int d4 = lane + k * 32;
        float4 x0 = xr0[d4];
        float4 x1 = xr1[d4];
        float4 x2 = xr2[d4];
        float4 x3 = xr3[d4];
        float4 wi = Wi[d4];
        float4 wj = Wj[d4];
        si0 += x0.x * wi.x + x0.y * wi.y + x0.z * wi.z + x0.w * wi.w;
        sj0 += x0.x * wj.x + x0.y * wj.y + x0.z * wj.z + x0.w * wj.w;
        si1 += x1.x * wi.x + x1.y * wi.y + x1.z * wi.z + x1.w * wi.w;
        sj1 += x1.x * wj.x + x1.y * wj.y + x1.z * wj.z + x1.w * wj.w;
        si2 += x2.x * wi.x + x2.y * wi.y + x2.z * wi.z + x2.w * wi.w;
        sj2 += x2.x * wj.x + x2.y * wj.y + x2.z * wj.z + x2.w * wj.w;
        si3 += x3.x * wi.x + x3.y * wi.y + x3.z * wi.z + x3.w * wi.w;
        sj3 += x3.x * wj.x + x3.y * wj.y + x3.z * wj.z + x3.w * wj.w;
    }
#pragma unroll
    for (int o = 16; o; o >>= 1) {
        si0 += __shfl_down_sync(0xffffffffu, si0, o);
        sj0 += __shfl_down_sync(0xffffffffu, sj0, o);
        si1 += __shfl_down_sync(0xffffffffu, si1, o);
        sj1 += __shfl_down_sync(0xffffffffu, sj1, o);
        si2 += __shfl_down_sync(0xffffffffu, si2, o);
        sj2 += __shfl_down_sync(0xffffffffu, sj2, o);
        si3 += __shfl_down_sync(0xffffffffu, si3, o);
        sj3 += __shfl_down_sync(0xffffffffu, sj3, o);
    }
    if (lane == 0) {
        float b0 = bias[0];
        g_esi[row0]     = __expf(-(si0 + b0));
        g_esj[row0]     = __expf(-sj0);
        g_esi[row0 + 1] = __expf(-(si1 + b0));
        g_esj[row0 + 1] = __expf(-sj1);
        g_esi[row0 + 2] = __expf(-(si2 + b0));
        g_esj[row0 + 2] = __expf(-sj2);
        g_esi[row0 + 3] = __expf(-(si3 + b0));
        g_esj[row0 + 3] = __expf(-sj3);
    }
}

__device__ __forceinline__ float blend(float esi, float esj, float a) {
    // P * sigmoid(si+sj) + (1-P)*a, with sigmoid = 1/(1+esi*esj)
    return fmaf(P_ASEM, __frcp_rn(fmaf(esi, esj, 1.0f)), (1.0f - P_ASEM) * a);
}

// Kernel 2 (R5-exact config, best measured): one block per 2 consecutive rows
// (same batch). esj float4s loaded once serve both rows; 4 adj loads batched.
__global__ void __launch_bounds__(256) fuse_kernel(const float* __restrict__ adj,
                                                   float* __restrict__ out) {
    unsigned row0 = blockIdx.x * 2u;         // b*2048 + i, i even
    unsigned b_base = row0 & ~(NDIM - 1u);   // b*2048
    unsigned tid = threadIdx.x;

    float esi0 = g_esi[row0];
    float esi1 = g_esi[row0 + 1];

    const float4* adj0 = reinterpret_cast<const float4*>(adj) + (size_t)row0 * (NDIM / 4);
    const float4* adj1 = adj0 + (NDIM / 4);
    float4* out0 = reinterpret_cast<float4*>(out) + (size_t)row0 * (NDIM / 4);
    float4* out1 = out0 + (NDIM / 4);
    const float4* esj_row = reinterpret_cast<const float4*>(g_esj + b_base);

    // front-batched: 4 adj + 2 esj loads in flight
    float4 a00 = __ldcs(adj0 + tid);
    float4 a01 = __ldcs(adj0 + tid + 256);
    float4 a10 = __ldcs(adj1 + tid);
    float4 a11 = __ldcs(adj1 + tid + 256);
    float4 e0 = esj_row[tid];
    float4 e1 = esj_row[tid + 256];

    float4 o;
    o.x = blend(esi0, e0.x, a00.x);
    o.y = blend(esi0, e0.y, a00.y);
    o.z = blend(esi0, e0.z, a00.z);
    o.w = blend(esi0, e0.w, a00.w);
    __stcs(out0 + tid, o);

    o.x = blend(esi0, e1.x, a01.x);
    o.y = blend(esi0, e1.y, a01.y);
    o.z = blend(esi0, e1.z, a01.z);
    o.w = blend(esi0, e1.w, a01.w);
    __stcs(out0 + tid + 256, o);

    o.x = blend(esi1, e0.x, a10.x);
    o.y = blend(esi1, e0.y, a10.y);
    o.z = blend(esi1, e0.z, a10.z);
    o.w = blend(esi1, e0.w, a10.w);
    __stcs(out1 + tid, o);

    o.x = blend(esi1, e1.x, a11.x);
    o.y = blend(esi1, e1.y, a11.y);
    o.z = blend(esi1, e1.z, a11.z);
    o.w = blend(esi1, e1.w, a11.w);
    __stcs(out1 + tid + 256, o);
}

extern "C" void kernel_launch(void* const* d_in, const int* in_sizes, int n_in,
                              void* d_out, int out_size) {
    const float* x   = (const float*)d_in[0];  // (8, 2048, 512)
    const float* adj = (const float*)d_in[1];  // (8, 2048, 2048)
    const float* W   = (const float*)d_in[2];  // (1, 1024)
    const float* b   = (const float*)d_in[3];  // (1,)
    float* out = (float*)d_out;

    // Kernel 1: 16384 rows, 4 rows/warp, 8 warps/block -> 512 blocks
    row_dots_kernel<<<512, 256>>>(x, W, b);
    // Kernel 2: 2 rows per block -> 8192 blocks
    fuse_kernel<<<BDIM * NDIM / 2, 256>>>(adj, out);
}